// round 1
// baseline (speedup 1.0000x reference)
#include <cuda_runtime.h>
#include <math.h>

#define NROWS 32768      // 32 * 32 * 32 vectors
#define DDIM  256
#define KCODES 1024
#define HW    1024       // 32*32 spatial
#define CHW   (DDIM*HW)  // 262144
#define OUT_ELEMS 8388608

// ---- scratch (device globals; no allocation allowed) ----
__device__ float g_cnorm[KCODES];
__device__ float g_xnorm[NROWS];
__device__ int   g_idx[NROWS];
__device__ int   g_counts[KCODES];
__device__ float g_loss_part[NROWS];   // one partial per gather block (32768 blocks)

// ============================================================
// Kernel A: codebook row norms (sum of squares, mul-then-add like ref x**2 sum)
//           + zero the histogram (graph replays need re-zeroing every call)
// ============================================================
__global__ void prep_cnorm(const float* __restrict__ cb) {
    int w    = (blockIdx.x * blockDim.x + threadIdx.x) >> 5;
    int lane = threadIdx.x & 31;
    if (w >= KCODES) return;
    const float* row = cb + (size_t)w * DDIM;
    float s = 0.f;
    #pragma unroll
    for (int d = lane; d < DDIM; d += 32) {
        float v = row[d];
        s = __fadd_rn(s, __fmul_rn(v, v));
    }
    #pragma unroll
    for (int o = 16; o; o >>= 1) s += __shfl_down_sync(0xffffffffu, s, o);
    if (lane == 0) { g_cnorm[w] = s; g_counts[w] = 0; }
}

// ============================================================
// Kernel B: per-row ||x||^2.  One thread per row; sequential over d
// (coalesced across threads: consecutive threads = consecutive hw).
// ============================================================
__global__ void prep_xnorm(const float* __restrict__ x) {
    int n  = blockIdx.x * blockDim.x + threadIdx.x;          // < 32768
    int b  = n >> 10, hw = n & 1023;
    const float* p = x + (size_t)b * CHW + hw;
    float s = 0.f;
    #pragma unroll 8
    for (int d = 0; d < DDIM; d++) {
        float v = p[(size_t)d * HW];
        s = __fadd_rn(s, __fmul_rn(v, v));
    }
    g_xnorm[n] = s;
}

// ============================================================
// Kernel C: fused SGEMM (x_flat @ cb^T) + argmin + histogram.
// Block = 256 threads, tile = 128 rows x 128 codes, K-chunk = 8 (D loop).
// dist = fl( fl(xnorm + cnorm) - 2*dot )  -- same rounding structure as ref,
// first-index tie-break.
// ============================================================
__global__ __launch_bounds__(256, 2)
void argmin_kernel(const float* __restrict__ x, const float* __restrict__ cb) {
    __shared__ float xs[8][128];
    __shared__ float cs[8][128];
    __shared__ float red_v[128][17];   // +1 pad
    __shared__ int   red_i[128][17];

    const int tid = threadIdx.x;
    const int tx  = tid & 15;          // code group (8 codes each)
    const int ty  = tid >> 4;          // row group  (8 rows each)
    const int m0  = blockIdx.x * 128;

    float mn[8]; int mi[8];
    #pragma unroll
    for (int i = 0; i < 8; i++) { mn[i] = 3.4e38f; mi[i] = 0; }

    float xn[8];
    #pragma unroll
    for (int i = 0; i < 8; i++) xn[i] = g_xnorm[m0 + ty * 8 + i];

    // x-tile load mapping: thread -> (row lm, d-subblock ldg of 4)
    const int lm  = tid & 127;
    const int ldg = tid >> 7;                  // 0 or 1
    const int nrow = m0 + lm;
    const int xb = nrow >> 10, xhw = nrow & 1023;
    const float* xbase = x + (size_t)xb * CHW + xhw + (size_t)(ldg * 4) * HW;

    // cb-tile load mapping: thread -> (code ck, d offset cd), float4
    const int ck = tid >> 1;                   // 0..127
    const int cd = (tid & 1) * 4;

    for (int nt = 0; nt < KCODES; nt += 128) {
        float acc[8][8];
        #pragma unroll
        for (int i = 0; i < 8; i++)
            #pragma unroll
            for (int j = 0; j < 8; j++) acc[i][j] = 0.f;

        for (int dt = 0; dt < DDIM; dt += 8) {
            const float* xp = xbase + (size_t)dt * HW;
            #pragma unroll
            for (int q = 0; q < 4; q++) xs[ldg * 4 + q][lm] = xp[(size_t)q * HW];

            float4 cv = *(const float4*)(cb + (size_t)(nt + ck) * DDIM + dt + cd);
            cs[cd + 0][ck] = cv.x; cs[cd + 1][ck] = cv.y;
            cs[cd + 2][ck] = cv.z; cs[cd + 3][ck] = cv.w;
            __syncthreads();

            #pragma unroll
            for (int d = 0; d < 8; d++) {
                float a[8], bb[8];
                #pragma unroll
                for (int i = 0; i < 8; i++) a[i]  = xs[d][ty * 8 + i];
                #pragma unroll
                for (int j = 0; j < 8; j++) bb[j] = cs[d][tx * 8 + j];
                #pragma unroll
                for (int i = 0; i < 8; i++)
                    #pragma unroll
                    for (int j = 0; j < 8; j++)
                        acc[i][j] = fmaf(a[i], bb[j], acc[i][j]);
            }
            __syncthreads();
        }

        #pragma unroll
        for (int j = 0; j < 8; j++) {
            int   kk = nt + tx * 8 + j;
            float cn = g_cnorm[kk];
            #pragma unroll
            for (int i = 0; i < 8; i++) {
                float t    = __fadd_rn(xn[i], cn);           // rounds at ~256 like ref
                float dist = __fadd_rn(t, -2.0f * acc[i][j]); // 2*acc exact
                if (dist < mn[i]) { mn[i] = dist; mi[i] = kk; }  // strict: keeps lowest k
            }
        }
    }

    #pragma unroll
    for (int i = 0; i < 8; i++) {
        red_v[ty * 8 + i][tx] = mn[i];
        red_i[ty * 8 + i][tx] = mi[i];
    }
    __syncthreads();
    if (tid < 128) {
        float best = red_v[tid][0]; int bi = red_i[tid][0];
        #pragma unroll
        for (int t = 1; t < 16; t++) {
            float v = red_v[tid][t]; int ii = red_i[tid][t];
            if (v < best || (v == best && ii < bi)) { best = v; bi = ii; }
        }
        g_idx[m0 + tid] = bi;
        atomicAdd(&g_counts[bi], 1);
    }
}

// ============================================================
// Kernel D: gather + straight-through output + loss partials.
// out = x + fl(q - x)  (bit-faithful to reference's STE expression)
// ============================================================
__global__ void gather_kernel(const float* __restrict__ x,
                              const float* __restrict__ cb,
                              float* __restrict__ out) {
    __shared__ float wsum[8];
    int e  = blockIdx.x * 256 + threadIdx.x;   // < 8388608 exactly
    int hw = e & 1023;
    int d  = (e >> 10) & 255;
    int b  = e >> 18;
    int n  = (b << 10) | hw;
    int k  = g_idx[n];

    float q  = cb[(size_t)k * DDIM + d];
    float xv = x[e];
    float r  = __fsub_rn(q, xv);        // stop_gradient(quantized - inputs)
    out[e]   = __fadd_rn(xv, r);        // straight-through estimator
    float s  = __fmul_rn(r, r);         // (q - x)^2 for loss

    #pragma unroll
    for (int o = 16; o; o >>= 1) s += __shfl_down_sync(0xffffffffu, s, o);
    if ((threadIdx.x & 31) == 0) wsum[threadIdx.x >> 5] = s;
    __syncthreads();
    if (threadIdx.x < 8) {
        float v = wsum[threadIdx.x];
        #pragma unroll
        for (int o = 4; o; o >>= 1) v += __shfl_down_sync(0xffu, v, o);
        if (threadIdx.x == 0) g_loss_part[blockIdx.x] = v;
    }
}

// ============================================================
// Kernel E: finalize loss + perplexity into the output tail.
// ============================================================
__global__ void finalize_kernel(float* __restrict__ out, int loss_off) {
    __shared__ double sh[256];
    int tid = threadIdx.x;

    double ls = 0.0;
    for (int i = tid; i < NROWS; i += 256) ls += (double)g_loss_part[i];
    double es = 0.0;
    for (int k = tid; k < KCODES; k += 256) {
        double p = (double)g_counts[k] * (1.0 / 32768.0);
        es += p * log(p + 1e-10);
    }

    sh[tid] = ls; __syncthreads();
    for (int s2 = 128; s2; s2 >>= 1) { if (tid < s2) sh[tid] += sh[tid + s2]; __syncthreads(); }
    double total_loss = sh[0];
    __syncthreads();

    sh[tid] = es; __syncthreads();
    for (int s2 = 128; s2; s2 >>= 1) { if (tid < s2) sh[tid] += sh[tid + s2]; __syncthreads(); }

    if (tid == 0) {
        double mean = total_loss / (double)OUT_ELEMS;   // mean((q-x)^2)
        // loss = q_latent + 0.25 * e_latent, both equal mean numerically
        out[loss_off]     = (float)(mean + 0.25 * mean);
        out[loss_off + 1] = (float)exp(-sh[0]);
    }
}

// ============================================================
extern "C" void kernel_launch(void* const* d_in, const int* in_sizes, int n_in,
                              void* d_out, int out_size) {
    const float* x  = (const float*)d_in[0];   // [32,256,32,32]
    const float* cb = (const float*)d_in[1];   // [1024,256]
    float* out = (float*)d_out;

    prep_cnorm<<<(KCODES * 32 + 255) / 256, 256>>>(cb);     // 1024 warps
    prep_xnorm<<<NROWS / 256, 256>>>(x);                    // 128 blocks
    argmin_kernel<<<NROWS / 128, 256>>>(x, cb);             // 256 blocks
    gather_kernel<<<OUT_ELEMS / 256, 256>>>(x, cb, out);    // 32768 blocks
    finalize_kernel<<<1, 256>>>(out, out_size - 2);
}